// round 11
// baseline (speedup 1.0000x reference)
#include <cuda_runtime.h>
#include <cstdint>

// Problem geometry (fixed by the reference)
#define WIDTH   1000
#define HEIGHT  1000
#define PS      5
#define NT      10
#define PPR     (WIDTH / PS)          // 200 patches per patch-row
#define NPIX    (WIDTH * HEIGHT)      // 1,000,000

constexpr int PATCHES_PER_BLOCK = 50;
constexpr int COLS_PER_BLOCK    = PATCHES_PER_BLOCK * PS;   // 250
constexpr int SEGS              = WIDTH / COLS_PER_BLOCK;   // 4
constexpr int THREADS           = 256;
constexpr int COEF_PER_PATCH    = 3 * NT * 2;               // 60 floats = 240 B
constexpr int COEF_BYTES        = PATCHES_PER_BLOCK * COEF_PER_PATCH * 4; // 12000
constexpr int PIXROW_BYTES      = COLS_PER_BLOCK * 8;       // 2000 (16B-aligned src!)
constexpr unsigned TX_BYTES     = COEF_BYTES + PS * PIXROW_BYTES;  // 22000

using ull = unsigned long long;

// Packed dual-FMA on the f32x2 pipe (ptxas never auto-fuses this).
__device__ __forceinline__ ull fma2(ull a, ull b, ull c) {
    ull d;
    asm("fma.rn.f32x2 %0, %1, %2, %3;" : "=l"(d) : "l"(a), "l"(b), "l"(c));
    return d;
}
__device__ __forceinline__ void unpack2(ull h, float& lo, float& hi) {
    asm("mov.b64 {%0, %1}, %2;" : "=f"(lo), "=f"(hi) : "l"(h));
}
__device__ __forceinline__ uint32_t smem_u32(const void* p) {
    return (uint32_t)__cvta_generic_to_shared(p);
}
__device__ __forceinline__ void bulk_g2s(void* smem_dst, const void* gmem_src,
                                         unsigned bytes, uint32_t mbar) {
    asm volatile(
        "cp.async.bulk.shared::cta.global.mbarrier::complete_tx::bytes "
        "[%0], [%1], %2, [%3];"
        :: "r"(smem_u32(smem_dst)), "l"(gmem_src), "r"(bytes), "r"(mbar)
        : "memory");
}

__global__ __launch_bounds__(THREADS, 6)   // regs<=42 -> 6 CTAs/SM -> one wave of 800
void ts_approx_kernel(const float* __restrict__ pix,     // [NPIX, 2]
                      const float* __restrict__ coef,    // [NPATCH, 3, NT, 2]
                      const float* __restrict__ bias,    // [NPATCH, 3]
                      float* __restrict__ out)           // [3, NPIX]
{
    __shared__ alignas(16) float4 s_coef[PATCHES_PER_BLOCK * 15];   // 12000 B
    __shared__ alignas(16) ull    s_pix[PS][COLS_PER_BLOCK];        // 10000 B
    __shared__ alignas(8)  ull    s_mbar;

    const int b      = blockIdx.x;
    const int pr     = b / SEGS;                  // patch-row 0..199
    const int seg    = b % SEGS;                  // 0..3
    const int row0   = pr * PS;
    const int c      = threadIdx.x;               // 0..249 active
    const int patch0 = pr * PPR + seg * PATCHES_PER_BLOCK;
    const int col0   = seg * COLS_PER_BLOCK;
    const int n0     = row0 * WIDTH + col0 + c;

    // Bias via LDG early (tiny, 5-lane L1 broadcast); latency hides under the bulk wait.
    float bg[3];
    if (c < COLS_PER_BLOCK) {
        const int pat = patch0 + c / PS;
        #pragma unroll
        for (int ch = 0; ch < 3; ch++)
            bg[ch] = __ldg(&bias[pat * 3 + ch]);
    }

    // ── All input staging through the TMA engine: ZERO per-thread copy ops.
    if (threadIdx.x == 0)
        asm volatile("mbarrier.init.shared.b64 [%0], 1;" :: "r"(smem_u32(&s_mbar)) : "memory");
    __syncthreads();
    if (threadIdx.x == 0) {
        const uint32_t mb = smem_u32(&s_mbar);
        asm volatile("mbarrier.arrive.expect_tx.shared.b64 _, [%0], %1;"
                     :: "r"(mb), "r"(TX_BYTES) : "memory");
        // Coefficients: one contiguous 12000B span (patch0*240 is 16B-aligned).
        bulk_g2s(s_coef, (const char*)coef + (size_t)patch0 * 240, COEF_BYTES, mb);
        // Pixels: 5 rows x 2000B, each span 16B-aligned ((row*1000+seg*250)*8).
        #pragma unroll
        for (int r = 0; r < PS; r++)
            bulk_g2s(&s_pix[r][0],
                     (const char*)pix + ((size_t)(row0 + r) * WIDTH + col0) * 8,
                     PIXROW_BYTES, mb);
    }

    // Wait for all 22000 bytes (acquire orders the smem reads below).
    {
        const uint32_t mb = smem_u32(&s_mbar);
        asm volatile(
            "{\n\t.reg .pred P;\n"
            "W%=:\n\t"
            "mbarrier.try_wait.parity.acquire.cta.shared::cta.b64 P, [%0], 0, 0x989680;\n\t"
            "@!P bra W%=;\n\t}"
            :: "r"(mb) : "memory");
    }

    if (c >= COLS_PER_BLOCK) return;

    const int pl = c / PS;                        // local patch 0..49

    // Pixel pairs from smem: lane-consecutive 8B -> conflict-free LDS.64.
    ull xy[PS];
    #pragma unroll
    for (int r = 0; r < PS; r++)
        xy[r] = s_pix[r][c];

    #pragma unroll
    for (int ch = 0; ch < 3; ch++) {
        // 5 x LDS.128; lane stride 240B across ~7 patches/warp -> conflict-free.
        const ulonglong2* cfc =
            reinterpret_cast<const ulonglong2*>(s_coef) + pl * 15 + ch * 5;
        const ulonglong2 u0 = cfc[0];   // (c0, c1) pairs (a_t, b_t)
        const ulonglong2 u1 = cfc[1];
        const ulonglong2 u2 = cfc[2];
        const ulonglong2 u3 = cfc[3];
        const ulonglong2 u4 = cfc[4];
        const float bch = bg[ch];

        // 5 independent packed Horner chains (one per row) -> ILP 5.
        #pragma unroll
        for (int r = 0; r < PS; r++) {
            ull h = u4.y;                  // (a9, b9)
            h = fma2(h, xy[r], u4.x);
            h = fma2(h, xy[r], u3.y);
            h = fma2(h, xy[r], u3.x);
            h = fma2(h, xy[r], u2.y);
            h = fma2(h, xy[r], u2.x);
            h = fma2(h, xy[r], u1.y);
            h = fma2(h, xy[r], u1.x);
            h = fma2(h, xy[r], u0.y);
            h = fma2(h, xy[r], u0.x);      // + (a0, b0)
            float hx, hy;
            unpack2(h, hx, hy);
            __stcs(&out[(size_t)ch * NPIX + n0 + r * WIDTH], hx + (hy + bch));
        }
    }
}

extern "C" void kernel_launch(void* const* d_in, const int* in_sizes, int n_in,
                              void* d_out, int out_size)
{
    const float* pix  = (const float*)d_in[0];   // [1e6, 2]
    const float* coef = (const float*)d_in[1];   // [40000, 3, 10, 2]
    const float* bias = (const float*)d_in[2];   // [40000, 3]
    float* out        = (float*)d_out;           // [3, 1e6]

    const int nblocks = (HEIGHT / PS) * SEGS;    // 200 * 4 = 800
    ts_approx_kernel<<<nblocks, THREADS>>>(pix, coef, bias, out);
}